// round 3
// baseline (speedup 1.0000x reference)
#include <cuda_runtime.h>
#include <math.h>

#define DM   768
#define NH   12
#define DK   64
#define BATCH 4
#define SEQ  2048
#define MTOT (BATCH*SEQ)   // 8192

// Scratch (device globals: allocation-free).
__device__ float g_q[(size_t)MTOT*DM];
__device__ float g_k[(size_t)MTOT*DM];
__device__ float g_v[(size_t)MTOT*DM];
__device__ float g_attn[(size_t)MTOT*DM];

// ---------------------------------------------------------------------------
// SGEMM: C = A(M x 768) @ W(768 x 768) + bias. BM=BN=128, BK=16, 256 thr, 8x8.
// HEAD_SPLIT writes C in (B, H, S, dk) layout for the attention kernel.
// ---------------------------------------------------------------------------
template<bool HEAD_SPLIT>
__global__ __launch_bounds__(256)
void gemm_bias(const float* __restrict__ A, const float* __restrict__ W,
               const float* __restrict__ bias, float* __restrict__ C)
{
    const int BM = 128, BN = 128, BK = 16;
    __shared__ float As[BK][BM + 4];
    __shared__ float Bs[BK][BN + 4];

    const int bm = blockIdx.y * BM;
    const int bn = blockIdx.x * BN;
    const int tid = threadIdx.x;
    const int tx = tid & 15;
    const int ty = tid >> 4;

    float acc[8][8];
#pragma unroll
    for (int i = 0; i < 8; i++)
#pragma unroll
        for (int j = 0; j < 8; j++) acc[i][j] = 0.f;

    const int a_r = tid >> 1;          // 0..127
    const int a_c = (tid & 1) * 4;     // 0 or 4
    const int b_r = tid >> 5;          // 0..7
    const int b_c = (tid & 31) * 4;    // 0..124

    for (int k0 = 0; k0 < DM; k0 += BK) {
        // A tile 128x16 -> As transposed
#pragma unroll
        for (int p = 0; p < 2; p++) {
            const int c = a_c + p * 8;
            float4 v = *(const float4*)(A + (size_t)(bm + a_r) * DM + k0 + c);
            As[c + 0][a_r] = v.x; As[c + 1][a_r] = v.y;
            As[c + 2][a_r] = v.z; As[c + 3][a_r] = v.w;
        }
        // W tile 16x128 -> Bs
#pragma unroll
        for (int p = 0; p < 2; p++) {
            const int r = b_r + p * 8;
            float4 v = *(const float4*)(W + (size_t)(k0 + r) * DM + bn + b_c);
            *(float4*)&Bs[r][b_c] = v;
        }
        __syncthreads();

#pragma unroll
        for (int k = 0; k < BK; k++) {
            float ar[8], br[8];
            *(float4*)&ar[0] = *(const float4*)&As[k][ty * 8];
            *(float4*)&ar[4] = *(const float4*)&As[k][ty * 8 + 4];
            *(float4*)&br[0] = *(const float4*)&Bs[k][tx * 8];
            *(float4*)&br[4] = *(const float4*)&Bs[k][tx * 8 + 4];
#pragma unroll
            for (int i = 0; i < 8; i++)
#pragma unroll
                for (int j = 0; j < 8; j++)
                    acc[i][j] = fmaf(ar[i], br[j], acc[i][j]);
        }
        __syncthreads();
    }

#pragma unroll
    for (int i = 0; i < 8; i++) {
        const int m = bm + ty * 8 + i;
#pragma unroll
        for (int j = 0; j < 8; j++) {
            const int n = bn + tx * 8 + j;
            const float v = acc[i][j] + bias[n];
            if (HEAD_SPLIT) {
                const int bb = m >> 11, ss = m & (SEQ - 1);
                const int hh = n >> 6,  dd = n & (DK - 1);
                C[((size_t)(bb * NH + hh) * SEQ + ss) * DK + dd] = v;
            } else {
                C[(size_t)m * DM + n] = v;
            }
        }
    }
}

// ---------------------------------------------------------------------------
// Flash attention (causal, online softmax). One block = (b, h, 64-row q tile).
// 256 threads as 16x16; each thread owns a 4x4 patch of the 64x64 score tile
// and a 4x4 patch of the 64x64 output tile.
// ---------------------------------------------------------------------------
#define TS  64
#define PAD 65   // stride 65: 2-way-max LDS bank conflicts

__device__ __forceinline__ float rmax16(float v) {
#pragma unroll
    for (int off = 8; off > 0; off >>= 1)
        v = fmaxf(v, __shfl_xor_sync(0xffffffffu, v, off, 16));
    return v;
}
__device__ __forceinline__ float rsum16(float v) {
#pragma unroll
    for (int off = 8; off > 0; off >>= 1)
        v += __shfl_xor_sync(0xffffffffu, v, off, 16);
    return v;
}

__global__ __launch_bounds__(256)
void attn_kernel()
{
    extern __shared__ float sm[];
    float* Qs = sm;                  // 64 x 65
    float* Ks = sm + TS * PAD;
    float* Vs = sm + 2 * TS * PAD;
    float* Ps = sm + 3 * TS * PAD;

    const int qi = blockIdx.x;
    const int h  = blockIdx.y;
    const int b  = blockIdx.z;
    const int tid = threadIdx.x;
    const int tx = tid & 15;
    const int ty = tid >> 4;

    const float* Qg = g_q + (size_t)((b * NH + h) * SEQ) * DK;
    const float* Kg = g_k + (size_t)((b * NH + h) * SEQ) * DK;
    const float* Vg = g_v + (size_t)((b * NH + h) * SEQ) * DK;

    // Load Q tile: thread -> row tid>>2, 16 consecutive floats at (tid&3)*16
    const int lr = tid >> 2;
    const int lc = (tid & 3) * 16;
    {
        const float4* src = (const float4*)(Qg + (size_t)(qi * TS + lr) * DK + lc);
#pragma unroll
        for (int i = 0; i < 4; i++) {
            float4 t = src[i];
            Qs[lr * PAD + lc + i * 4 + 0] = t.x;
            Qs[lr * PAD + lc + i * 4 + 1] = t.y;
            Qs[lr * PAD + lc + i * 4 + 2] = t.z;
            Qs[lr * PAD + lc + i * 4 + 3] = t.w;
        }
    }

    float m_i[4], l_i[4], o[4][4];
#pragma unroll
    for (int i = 0; i < 4; i++) {
        m_i[i] = -INFINITY; l_i[i] = 0.f;
#pragma unroll
        for (int c = 0; c < 4; c++) o[i][c] = 0.f;
    }

    const float scale = 0.125f;  // 1/sqrt(64)

    for (int j = 0; j <= qi; j++) {
        __syncthreads();  // prev-iter PV readers done (also covers Q load on iter 0)
        {
            const float4* ks = (const float4*)(Kg + (size_t)(j * TS + lr) * DK + lc);
            const float4* vs = (const float4*)(Vg + (size_t)(j * TS + lr) * DK + lc);
#pragma unroll
            for (int i = 0; i < 4; i++) {
                float4 tk = ks[i], tv = vs[i];
                Ks[lr * PAD + lc + i * 4 + 0] = tk.x;
                Ks[lr * PAD + lc + i * 4 + 1] = tk.y;
                Ks[lr * PAD + lc + i * 4 + 2] = tk.z;
                Ks[lr * PAD + lc + i * 4 + 3] = tk.w;
                Vs[lr * PAD + lc + i * 4 + 0] = tv.x;
                Vs[lr * PAD + lc + i * 4 + 1] = tv.y;
                Vs[lr * PAD + lc + i * 4 + 2] = tv.z;
                Vs[lr * PAD + lc + i * 4 + 3] = tv.w;
            }
        }
        __syncthreads();

        // S = Q . K^T (4x4 per thread)
        float s[4][4];
#pragma unroll
        for (int i = 0; i < 4; i++)
#pragma unroll
            for (int c = 0; c < 4; c++) s[i][c] = 0.f;

#pragma unroll 8
        for (int d = 0; d < DK; d++) {
            float qv[4], kv[4];
#pragma unroll
            for (int i = 0; i < 4; i++) qv[i] = Qs[(ty * 4 + i) * PAD + d];
#pragma unroll
            for (int c = 0; c < 4; c++) kv[c] = Ks[(tx * 4 + c) * PAD + d];
#pragma unroll
            for (int i = 0; i < 4; i++)
#pragma unroll
                for (int c = 0; c < 4; c++)
                    s[i][c] = fmaf(qv[i], kv[c], s[i][c]);
        }

        // scale + causal mask (diagonal tile only)
        if (j == qi) {
#pragma unroll
            for (int i = 0; i < 4; i++) {
                const int qr = ty * 4 + i;
#pragma unroll
                for (int c = 0; c < 4; c++) {
                    const int kc = tx * 4 + c;
                    s[i][c] = (kc <= qr) ? s[i][c] * scale : -INFINITY;
                }
            }
        } else {
#pragma unroll
            for (int i = 0; i < 4; i++)
#pragma unroll
                for (int c = 0; c < 4; c++) s[i][c] *= scale;
        }

        // online softmax
#pragma unroll
        for (int i = 0; i < 4; i++) {
            float rm = fmaxf(fmaxf(s[i][0], s[i][1]), fmaxf(s[i][2], s[i][3]));
            rm = rmax16(rm);
            const float nm = fmaxf(m_i[i], rm);
            float rs = 0.f;
#pragma unroll
            for (int c = 0; c < 4; c++) {
                s[i][c] = __expf(s[i][c] - nm);   // masked -> exp(-inf) = 0
                rs += s[i][c];
            }
            rs = rsum16(rs);
            const float alpha = __expf(m_i[i] - nm);
            l_i[i] = l_i[i] * alpha + rs;
#pragma unroll
            for (int c = 0; c < 4; c++) o[i][c] *= alpha;
            m_i[i] = nm;
        }

        // P to shared
#pragma unroll
        for (int i = 0; i < 4; i++)
#pragma unroll
            for (int c = 0; c < 4; c++)
                Ps[(ty * 4 + i) * PAD + tx * 4 + c] = s[i][c];
        __syncthreads();

        // O += P . V
#pragma unroll 8
        for (int k = 0; k < TS; k++) {
            float pv[4], vv[4];
#pragma unroll
            for (int i = 0; i < 4; i++) pv[i] = Ps[(ty * 4 + i) * PAD + k];
#pragma unroll
            for (int c = 0; c < 4; c++) vv[c] = Vs[k * PAD + tx * 4 + c];
#pragma unroll
            for (int i = 0; i < 4; i++)
#pragma unroll
                for (int c = 0; c < 4; c++)
                    o[i][c] = fmaf(pv[i], vv[c], o[i][c]);
        }
    }

    // epilogue: normalize, write to (B, S, D) layout for the output projection
#pragma unroll
    for (int i = 0; i < 4; i++) {
        const float inv = 1.f / l_i[i];
        const int srow = qi * TS + ty * 4 + i;
#pragma unroll
        for (int c = 0; c < 4; c++) {
            g_attn[((size_t)(b * SEQ) + srow) * DM + h * DK + tx * 4 + c] = o[i][c] * inv;
        }
    }
}

// ---------------------------------------------------------------------------

extern "C" void kernel_launch(void* const* d_in, const int* in_sizes, int n_in,
                              void* d_out, int out_size)
{
    const float* x  = (const float*)d_in[0];
    const float* Wq = (const float*)d_in[1];
    const float* bq = (const float*)d_in[2];
    const float* Wk = (const float*)d_in[3];
    const float* bk = (const float*)d_in[4];
    const float* Wv = (const float*)d_in[5];
    const float* bv = (const float*)d_in[6];
    const float* Wo = (const float*)d_in[7];
    const float* bo = (const float*)d_in[8];
    float* out = (float*)d_out;

    float *qp, *kp, *vp, *ap;
    cudaGetSymbolAddress((void**)&qp, g_q);
    cudaGetSymbolAddress((void**)&kp, g_k);
    cudaGetSymbolAddress((void**)&vp, g_v);
    cudaGetSymbolAddress((void**)&ap, g_attn);

    const dim3 ggrid(DM / 128, MTOT / 128);  // (6, 64)

    gemm_bias<true><<<ggrid, 256>>>(x, Wq, bq, qp);
    gemm_bias<true><<<ggrid, 256>>>(x, Wk, bk, kp);
    gemm_bias<true><<<ggrid, 256>>>(x, Wv, bv, vp);

    const int smem_bytes = 4 * TS * PAD * (int)sizeof(float);  // 66560
    cudaFuncSetAttribute(attn_kernel, cudaFuncAttributeMaxDynamicSharedMemorySize,
                         smem_bytes);
    attn_kernel<<<dim3(SEQ / TS, NH, BATCH), 256, smem_bytes>>>();

    gemm_bias<false><<<ggrid, 256>>>(ap, Wo, bo, out);
}

// round 4
// speedup vs baseline: 1.0652x; 1.0652x over previous
#include <cuda_runtime.h>
#include <math.h>
#include <stdint.h>

#define DM   768
#define NH   12
#define DK   64
#define BATCH 4
#define SEQ  2048
#define MTOT (BATCH*SEQ)   // 8192

// Scratch (device globals: allocation-free).
__device__ float g_q[(size_t)MTOT*DM];
__device__ float g_k[(size_t)MTOT*DM];
__device__ float g_v[(size_t)MTOT*DM];
__device__ float g_attn[(size_t)MTOT*DM];

// ---------------------------------------------------------------------------
// tf32 helpers
// ---------------------------------------------------------------------------
__device__ __forceinline__ uint32_t f2tf32(float x) {
    uint32_t r;
    asm("cvt.rna.tf32.f32 %0, %1;" : "=r"(r) : "f"(x));
    return r;
}

__device__ __forceinline__ void mma_tf32(float (&d)[4], const uint32_t (&a)[4],
                                         const uint32_t (&b)[2]) {
    asm volatile(
        "mma.sync.aligned.m16n8k8.row.col.f32.tf32.tf32.f32 "
        "{%0,%1,%2,%3}, {%4,%5,%6,%7}, {%8,%9}, {%0,%1,%2,%3};"
        : "+f"(d[0]), "+f"(d[1]), "+f"(d[2]), "+f"(d[3])
        : "r"(a[0]), "r"(a[1]), "r"(a[2]), "r"(a[3]), "r"(b[0]), "r"(b[1]));
}

// ---------------------------------------------------------------------------
// Split-precision tf32 GEMM: C = A(M x 768) @ W(768 x 768) + bias.
// BM=BN=128, BK=32, 256 threads (8 warps, each 64x32 warp tile).
// Each fp32 operand is split a = a_hi(tf32) + a_lo; D += AhBh + AhBl + AlBh.
// Error ~2^-22 — fp32-equivalent for this tolerance.
// HEAD_SPLIT writes C in (B, H, S, dk) layout for the attention kernel.
// ---------------------------------------------------------------------------
#define LDA 136   // 128 + 8 -> bank-shift 8 per k-row: frag loads hit all 32 banks

template<bool HEAD_SPLIT>
__global__ __launch_bounds__(256)
void gemm_tf32(const float* __restrict__ A, const float* __restrict__ W,
               const float* __restrict__ bias, float* __restrict__ C)
{
    const int BM = 128, BN = 128, BK = 32;
    extern __shared__ float sm[];
    float* Ah = sm;                    // [BK][LDA], A^T tile (k-major)
    float* Al = Ah + BK * LDA;
    float* Bh = Al + BK * LDA;         // [BK][LDA], B tile (k rows, n cols)
    float* Bl = Bh + BK * LDA;

    const int bm = blockIdx.y * BM;
    const int bn = blockIdx.x * BN;
    const int tid  = threadIdx.x;
    const int lane = tid & 31;
    const int w    = tid >> 5;
    const int grp  = lane >> 2;   // 0..7
    const int tig  = lane & 3;    // 0..3
    const int wm   = (w & 1) * 64;   // warp M offset in block tile
    const int wn   = (w >> 1) * 32;  // warp N offset in block tile

    float acc[4][4][4];
#pragma unroll
    for (int mi = 0; mi < 4; mi++)
#pragma unroll
        for (int ni = 0; ni < 4; ni++)
#pragma unroll
            for (int e = 0; e < 4; e++) acc[mi][ni][e] = 0.f;

    // global->shared load indices
    const int ar = tid >> 1;           // 0..127 (A tile row)
    const int ac = (tid & 1) * 16;     // A tile col base
    const int br = tid >> 3;           // 0..31  (B tile row)
    const int bc = (tid & 7) * 16;     // B tile col base

    for (int k0 = 0; k0 < DM; k0 += BK) {
        // A tile 128x32 -> split + transpose into Ah/Al[k][m]
#pragma unroll
        for (int p = 0; p < 4; p++) {
            float4 v = *(const float4*)(A + (size_t)(bm + ar) * DM + k0 + ac + p * 4);
            float vv[4] = {v.x, v.y, v.z, v.w};
#pragma unroll
            for (int q = 0; q < 4; q++) {
                const int k = ac + p * 4 + q;
                const float hf = __uint_as_float(f2tf32(vv[q]));
                Ah[k * LDA + ar] = hf;
                Al[k * LDA + ar] = vv[q] - hf;
            }
        }
        // B tile 32x128 -> split into Bh/Bl[k][n]
#pragma unroll
        for (int p = 0; p < 4; p++) {
            float4 v = *(const float4*)(W + (size_t)(k0 + br) * DM + bn + bc + p * 4);
            float vv[4] = {v.x, v.y, v.z, v.w};
#pragma unroll
            for (int q = 0; q < 4; q++) {
                const float hf = __uint_as_float(f2tf32(vv[q]));
                Bh[br * LDA + bc + p * 4 + q] = hf;
                Bl[br * LDA + bc + p * 4 + q] = vv[q] - hf;
            }
        }
        __syncthreads();

#pragma unroll
        for (int ks = 0; ks < BK; ks += 8) {
            uint32_t a_h[4][4], a_l[4][4], b_h[4][2], b_l[4][2];
#pragma unroll
            for (int mi = 0; mi < 4; mi++) {
                const int m0 = wm + mi * 16 + grp;
                const int r0 = (ks + tig) * LDA;
                const int r4 = (ks + tig + 4) * LDA;
                a_h[mi][0] = __float_as_uint(Ah[r0 + m0]);
                a_h[mi][1] = __float_as_uint(Ah[r0 + m0 + 8]);
                a_h[mi][2] = __float_as_uint(Ah[r4 + m0]);
                a_h[mi][3] = __float_as_uint(Ah[r4 + m0 + 8]);
                a_l[mi][0] = __float_as_uint(Al[r0 + m0]);
                a_l[mi][1] = __float_as_uint(Al[r0 + m0 + 8]);
                a_l[mi][2] = __float_as_uint(Al[r4 + m0]);
                a_l[mi][3] = __float_as_uint(Al[r4 + m0 + 8]);
            }
#pragma unroll
            for (int ni = 0; ni < 4; ni++) {
                const int n0 = wn + ni * 8 + grp;
                b_h[ni][0] = __float_as_uint(Bh[(ks + tig) * LDA + n0]);
                b_h[ni][1] = __float_as_uint(Bh[(ks + tig + 4) * LDA + n0]);
                b_l[ni][0] = __float_as_uint(Bl[(ks + tig) * LDA + n0]);
                b_l[ni][1] = __float_as_uint(Bl[(ks + tig + 4) * LDA + n0]);
            }
#pragma unroll
            for (int mi = 0; mi < 4; mi++)
#pragma unroll
                for (int ni = 0; ni < 4; ni++) {
                    mma_tf32(acc[mi][ni], a_h[mi], b_h[ni]);
                    mma_tf32(acc[mi][ni], a_h[mi], b_l[ni]);
                    mma_tf32(acc[mi][ni], a_l[mi], b_h[ni]);
                }
        }
        __syncthreads();
    }

    // epilogue: bias add + (optional) head-split layout
#pragma unroll
    for (int mi = 0; mi < 4; mi++) {
#pragma unroll
        for (int ni = 0; ni < 4; ni++) {
#pragma unroll
            for (int e = 0; e < 4; e++) {
                const int m = bm + wm + mi * 16 + grp + (e >> 1) * 8;
                const int n = bn + wn + ni * 8 + tig * 2 + (e & 1);
                const float v = acc[mi][ni][e] + bias[n];
                if (HEAD_SPLIT) {
                    const int bb = m >> 11, ss = m & (SEQ - 1);
                    const int hh = n >> 6,  dd = n & (DK - 1);
                    C[((size_t)(bb * NH + hh) * SEQ + ss) * DK + dd] = v;
                } else {
                    C[(size_t)m * DM + n] = v;
                }
            }
        }
    }
}

// ---------------------------------------------------------------------------
// Flash attention (causal, online softmax). One block = (b, h, 64-row q tile).
// 256 threads as 16x16; each thread owns a 4x4 patch. (Unchanged from R3.)
// ---------------------------------------------------------------------------
#define TS  64
#define PAD 65

__device__ __forceinline__ float rmax16(float v) {
#pragma unroll
    for (int off = 8; off > 0; off >>= 1)
        v = fmaxf(v, __shfl_xor_sync(0xffffffffu, v, off, 16));
    return v;
}
__device__ __forceinline__ float rsum16(float v) {
#pragma unroll
    for (int off = 8; off > 0; off >>= 1)
        v += __shfl_xor_sync(0xffffffffu, v, off, 16);
    return v;
}

__global__ __launch_bounds__(256)
void attn_kernel()
{
    extern __shared__ float sm[];
    float* Qs = sm;                  // 64 x 65
    float* Ks = sm + TS * PAD;
    float* Vs = sm + 2 * TS * PAD;
    float* Ps = sm + 3 * TS * PAD;

    const int qi = blockIdx.x;
    const int h  = blockIdx.y;
    const int b  = blockIdx.z;
    const int tid = threadIdx.x;
    const int tx = tid & 15;
    const int ty = tid >> 4;

    const float* Qg = g_q + (size_t)((b * NH + h) * SEQ) * DK;
    const float* Kg = g_k + (size_t)((b * NH + h) * SEQ) * DK;
    const float* Vg = g_v + (size_t)((b * NH + h) * SEQ) * DK;

    const int lr = tid >> 2;
    const int lc = (tid & 3) * 16;
    {
        const float4* src = (const float4*)(Qg + (size_t)(qi * TS + lr) * DK + lc);
#pragma unroll
        for (int i = 0; i < 4; i++) {
            float4 t = src[i];
            Qs[lr * PAD + lc + i * 4 + 0] = t.x;
            Qs[lr * PAD + lc + i * 4 + 1] = t.y;
            Qs[lr * PAD + lc + i * 4 + 2] = t.z;
            Qs[lr * PAD + lc + i * 4 + 3] = t.w;
        }
    }

    float m_i[4], l_i[4], o[4][4];
#pragma unroll
    for (int i = 0; i < 4; i++) {
        m_i[i] = -INFINITY; l_i[i] = 0.f;
#pragma unroll
        for (int c = 0; c < 4; c++) o[i][c] = 0.f;
    }

    const float scale = 0.125f;  // 1/sqrt(64)

    for (int j = 0; j <= qi; j++) {
        __syncthreads();
        {
            const float4* ks = (const float4*)(Kg + (size_t)(j * TS + lr) * DK + lc);
            const float4* vs = (const float4*)(Vg + (size_t)(j * TS + lr) * DK + lc);
#pragma unroll
            for (int i = 0; i < 4; i++) {
                float4 tk = ks[i], tv = vs[i];
                Ks[lr * PAD + lc + i * 4 + 0] = tk.x;
                Ks[lr * PAD + lc + i * 4 + 1] = tk.y;
                Ks[lr * PAD + lc + i * 4 + 2] = tk.z;
                Ks[lr * PAD + lc + i * 4 + 3] = tk.w;
                Vs[lr * PAD + lc + i * 4 + 0] = tv.x;
                Vs[lr * PAD + lc + i * 4 + 1] = tv.y;
                Vs[lr * PAD + lc + i * 4 + 2] = tv.z;
                Vs[lr * PAD + lc + i * 4 + 3] = tv.w;
            }
        }
        __syncthreads();

        float s[4][4];
#pragma unroll
        for (int i = 0; i < 4; i++)
#pragma unroll
            for (int c = 0; c < 4; c++) s[i][c] = 0.f;

#pragma unroll 8
        for (int d = 0; d < DK; d++) {
            float qv[4], kv[4];
#pragma unroll
            for (int i = 0; i < 4; i++) qv[i] = Qs[(ty * 4 + i) * PAD + d];
#pragma unroll
            for (int c = 0; c < 4; c++) kv[c] = Ks[(tx * 4 + c) * PAD + d];
#pragma unroll
            for (int i = 0; i < 4; i++)
#pragma unroll
                for (int c = 0; c < 4; c++)
                    s[i][c] = fmaf(qv[i], kv[c], s[i][c]);
        }

        if (j == qi) {
#pragma unroll
            for (int i = 0; i < 4; i++) {
                const int qr = ty * 4 + i;
#pragma unroll
                for (int c = 0; c < 4; c++) {
                    const int kc = tx * 4 + c;
                    s[i][c] = (kc <= qr) ? s[i][c] * scale : -INFINITY;
                }
            }
        } else {
#pragma unroll
            for (int i = 0; i < 4; i++)
#pragma unroll
                for (int c = 0; c < 4; c++) s[i][c] *= scale;
        }

#pragma unroll
        for (int i = 0; i < 4; i++) {
            float rm = fmaxf(fmaxf(s[i][0], s[i][1]), fmaxf(s[i][2], s[i][3]));
            rm = rmax16(rm);
            const float nm = fmaxf(m_i[i], rm);
            float rs = 0.f;
#pragma unroll
            for (int c = 0; c < 4; c++) {
                s[i][c] = __expf(s[i][c] - nm);
                rs += s[i][c];
            }
            rs = rsum16(rs);
            const float alpha = __expf(m_i[i] - nm);
            l_i[i] = l_i[i] * alpha + rs;
#pragma unroll
            for (int c = 0; c < 4; c++) o[i][c] *= alpha;
            m_i[i] = nm;
        }

#pragma unroll
        for (int i = 0; i < 4; i++)
#pragma unroll
            for (int c = 0; c < 4; c++)
                Ps[(ty * 4 + i) * PAD + tx * 4 + c] = s[i][c];
        __syncthreads();

#pragma unroll 8
        for (int k = 0; k < TS; k++) {
            float pv[4], vv[4];
#pragma unroll
            for (int i = 0; i < 4; i++) pv[i] = Ps[(ty * 4 + i) * PAD + k];
#pragma unroll
            for (int c = 0; c < 4; c++) vv[c] = Vs[k * PAD + tx * 4 + c];
#pragma unroll
            for (int i = 0; i < 4; i++)
#pragma unroll
                for (int c = 0; c < 4; c++)
                    o[i][c] = fmaf(pv[i], vv[c], o[i][c]);
        }
    }

#pragma unroll
    for (int i = 0; i < 4; i++) {
        const float inv = 1.f / l_i[i];
        const int srow = qi * TS + ty * 4 + i;
#pragma unroll
        for (int c = 0; c < 4; c++) {
            g_attn[((size_t)(b * SEQ) + srow) * DM + h * DK + tx * 4 + c] = o[i][c] * inv;
        }
    }
}

// ---------------------------------------------------------------------------

extern "C" void kernel_launch(void* const* d_in, const int* in_sizes, int n_in,
                              void* d_out, int out_size)
{
    const float* x  = (const float*)d_in[0];
    const float* Wq = (const float*)d_in[1];
    const float* bq = (const float*)d_in[2];
    const float* Wk = (const float*)d_in[3];
    const float* bk = (const float*)d_in[4];
    const float* Wv = (const float*)d_in[5];
    const float* bv = (const float*)d_in[6];
    const float* Wo = (const float*)d_in[7];
    const float* bo = (const float*)d_in[8];
    float* out = (float*)d_out;

    float *qp, *kp, *vp, *ap;
    cudaGetSymbolAddress((void**)&qp, g_q);
    cudaGetSymbolAddress((void**)&kp, g_k);
    cudaGetSymbolAddress((void**)&vp, g_v);
    cudaGetSymbolAddress((void**)&ap, g_attn);

    const dim3 ggrid(DM / 128, MTOT / 128);  // (6, 64)
    const int gemm_smem = 4 * 32 * LDA * (int)sizeof(float);  // 69632

    cudaFuncSetAttribute(gemm_tf32<true>,  cudaFuncAttributeMaxDynamicSharedMemorySize, gemm_smem);
    cudaFuncSetAttribute(gemm_tf32<false>, cudaFuncAttributeMaxDynamicSharedMemorySize, gemm_smem);

    gemm_tf32<true><<<ggrid, 256, gemm_smem>>>(x, Wq, bq, qp);
    gemm_tf32<true><<<ggrid, 256, gemm_smem>>>(x, Wk, bk, kp);
    gemm_tf32<true><<<ggrid, 256, gemm_smem>>>(x, Wv, bv, vp);

    const int smem_bytes = 4 * TS * PAD * (int)sizeof(float);  // 66560
    cudaFuncSetAttribute(attn_kernel, cudaFuncAttributeMaxDynamicSharedMemorySize,
                         smem_bytes);
    attn_kernel<<<dim3(SEQ / TS, NH, BATCH), 256, smem_bytes>>>();

    gemm_tf32<false><<<ggrid, 256, gemm_smem>>>(ap, Wo, bo, out);
}

// round 7
// speedup vs baseline: 1.3147x; 1.2342x over previous
#include <cuda_runtime.h>
#include <math.h>
#include <stdint.h>

#define DM   768
#define NH   12
#define DK   64
#define BATCH 4
#define SEQ  2048
#define MTOT (BATCH*SEQ)   // 8192

// Scratch (device globals: allocation-free).
__device__ float g_q[(size_t)MTOT*DM];
__device__ float g_k[(size_t)MTOT*DM];
__device__ float g_v[(size_t)MTOT*DM];
__device__ float g_attn[(size_t)MTOT*DM];

// ---------------------------------------------------------------------------
// tf32 helpers
// ---------------------------------------------------------------------------
__device__ __forceinline__ uint32_t f2tf32(float x) {
    uint32_t r;
    asm("cvt.rna.tf32.f32 %0, %1;" : "=r"(r) : "f"(x));
    return r;
}

__device__ __forceinline__ void mma_tf32(float (&d)[4], const uint32_t (&a)[4],
                                         const uint32_t (&b)[2]) {
    asm volatile(
        "mma.sync.aligned.m16n8k8.row.col.f32.tf32.tf32.f32 "
        "{%0,%1,%2,%3}, {%4,%5,%6,%7}, {%8,%9}, {%0,%1,%2,%3};"
        : "+f"(d[0]), "+f"(d[1]), "+f"(d[2]), "+f"(d[3])
        : "r"(a[0]), "r"(a[1]), "r"(a[2]), "r"(a[3]), "r"(b[0]), "r"(b[1]));
}

// ---------------------------------------------------------------------------
// Split-precision tf32 GEMM: C = A(M x 768) @ W(768 x 768) + bias.
// (unchanged from R4)
// ---------------------------------------------------------------------------
#define LDA 136

template<bool HEAD_SPLIT>
__global__ __launch_bounds__(256)
void gemm_tf32(const float* __restrict__ A, const float* __restrict__ W,
               const float* __restrict__ bias, float* __restrict__ C)
{
    const int BM = 128, BN = 128, BK = 32;
    extern __shared__ float sm[];
    float* Ah = sm;
    float* Al = Ah + BK * LDA;
    float* Bh = Al + BK * LDA;
    float* Bl = Bh + BK * LDA;

    const int bm = blockIdx.y * BM;
    const int bn = blockIdx.x * BN;
    const int tid  = threadIdx.x;
    const int lane = tid & 31;
    const int w    = tid >> 5;
    const int grp  = lane >> 2;
    const int tig  = lane & 3;
    const int wm   = (w & 1) * 64;
    const int wn   = (w >> 1) * 32;

    float acc[4][4][4];
#pragma unroll
    for (int mi = 0; mi < 4; mi++)
#pragma unroll
        for (int ni = 0; ni < 4; ni++)
#pragma unroll
            for (int e = 0; e < 4; e++) acc[mi][ni][e] = 0.f;

    const int ar = tid >> 1;
    const int ac = (tid & 1) * 16;
    const int br = tid >> 3;
    const int bc = (tid & 7) * 16;

    for (int k0 = 0; k0 < DM; k0 += BK) {
#pragma unroll
        for (int p = 0; p < 4; p++) {
            float4 v = *(const float4*)(A + (size_t)(bm + ar) * DM + k0 + ac + p * 4);
            float vv[4] = {v.x, v.y, v.z, v.w};
#pragma unroll
            for (int q = 0; q < 4; q++) {
                const int k = ac + p * 4 + q;
                const float hf = __uint_as_float(f2tf32(vv[q]));
                Ah[k * LDA + ar] = hf;
                Al[k * LDA + ar] = vv[q] - hf;
            }
        }
#pragma unroll
        for (int p = 0; p < 4; p++) {
            float4 v = *(const float4*)(W + (size_t)(k0 + br) * DM + bn + bc + p * 4);
            float vv[4] = {v.x, v.y, v.z, v.w};
#pragma unroll
            for (int q = 0; q < 4; q++) {
                const float hf = __uint_as_float(f2tf32(vv[q]));
                Bh[br * LDA + bc + p * 4 + q] = hf;
                Bl[br * LDA + bc + p * 4 + q] = vv[q] - hf;
            }
        }
        __syncthreads();

#pragma unroll
        for (int ks = 0; ks < BK; ks += 8) {
            uint32_t a_h[4][4], a_l[4][4], b_h[4][2], b_l[4][2];
#pragma unroll
            for (int mi = 0; mi < 4; mi++) {
                const int m0 = wm + mi * 16 + grp;
                const int r0 = (ks + tig) * LDA;
                const int r4 = (ks + tig + 4) * LDA;
                a_h[mi][0] = __float_as_uint(Ah[r0 + m0]);
                a_h[mi][1] = __float_as_uint(Ah[r0 + m0 + 8]);
                a_h[mi][2] = __float_as_uint(Ah[r4 + m0]);
                a_h[mi][3] = __float_as_uint(Ah[r4 + m0 + 8]);
                a_l[mi][0] = __float_as_uint(Al[r0 + m0]);
                a_l[mi][1] = __float_as_uint(Al[r0 + m0 + 8]);
                a_l[mi][2] = __float_as_uint(Al[r4 + m0]);
                a_l[mi][3] = __float_as_uint(Al[r4 + m0 + 8]);
            }
#pragma unroll
            for (int ni = 0; ni < 4; ni++) {
                const int n0 = wn + ni * 8 + grp;
                b_h[ni][0] = __float_as_uint(Bh[(ks + tig) * LDA + n0]);
                b_h[ni][1] = __float_as_uint(Bh[(ks + tig + 4) * LDA + n0]);
                b_l[ni][0] = __float_as_uint(Bl[(ks + tig) * LDA + n0]);
                b_l[ni][1] = __float_as_uint(Bl[(ks + tig + 4) * LDA + n0]);
            }
#pragma unroll
            for (int mi = 0; mi < 4; mi++)
#pragma unroll
                for (int ni = 0; ni < 4; ni++) {
                    mma_tf32(acc[mi][ni], a_h[mi], b_h[ni]);
                    mma_tf32(acc[mi][ni], a_h[mi], b_l[ni]);
                    mma_tf32(acc[mi][ni], a_l[mi], b_h[ni]);
                }
        }
        __syncthreads();
    }

#pragma unroll
    for (int mi = 0; mi < 4; mi++) {
#pragma unroll
        for (int ni = 0; ni < 4; ni++) {
#pragma unroll
            for (int e = 0; e < 4; e++) {
                const int m = bm + wm + mi * 16 + grp + (e >> 1) * 8;
                const int n = bn + wn + ni * 8 + tig * 2 + (e & 1);
                const float v = acc[mi][ni][e] + bias[n];
                if (HEAD_SPLIT) {
                    const int bb = m >> 11, ss = m & (SEQ - 1);
                    const int hh = n >> 6,  dd = n & (DK - 1);
                    C[((size_t)(bb * NH + hh) * SEQ + ss) * DK + dd] = v;
                } else {
                    C[(size_t)m * DM + n] = v;
                }
            }
        }
    }
}

// ---------------------------------------------------------------------------
// Tensor-core flash attention (causal, online softmax, split-tf32 MMA).
// Block = (b, h, 128-row q tile); 8 warps as 4(m) x 2(n); 32x32 warp tiles.
// ---------------------------------------------------------------------------
#define QT   128
#define KT   64
#define APAD 68

__global__ __launch_bounds__(256)
void attn_mma()
{
    extern __shared__ float sm[];
    float* Qh = sm;                       // 128 x 68
    float* Ql = Qh + QT * APAD;
    float* Kh = Ql + QT * APAD;           // 64 x 68
    float* Kl = Kh + KT * APAD;
    float* Vh = Kl + KT * APAD;           // 64 x 68
    float* Vl = Vh + KT * APAD;
    float* Ph = Vl + KT * APAD;           // 128 x 68
    float* Pl = Ph + QT * APAD;
    float* redm = Pl + QT * APAD;         // 2 x 128
    float* reds = redm + 2 * QT;          // 2 x 128

    const int qi = (SEQ / QT - 1) - blockIdx.x;   // heavy tiles first (LPT)
    const int h  = blockIdx.y;
    const int b  = blockIdx.z;
    const int tid  = threadIdx.x;
    const int lane = tid & 31;
    const int w    = tid >> 5;
    const int grp  = lane >> 2;
    const int tig  = lane & 3;
    const int wm   = (w & 3) * 32;        // warp m offset (0..96)
    const int wn   = (w >> 2) * 32;       // warp n offset (0 or 32)
    const int warp_n = w >> 2;

    const float* Qg = g_q + ((size_t)(b * NH + h) * SEQ + (size_t)qi * QT) * DK;
    const float* Kg = g_k + (size_t)(b * NH + h) * SEQ * DK;
    const float* Vg = g_v + (size_t)(b * NH + h) * SEQ * DK;

    // ---- load Q tile (128 x 64), split hi/lo ----
    {
        const int r  = tid >> 1;
        const int c0 = (tid & 1) * 32;
#pragma unroll
        for (int p = 0; p < 8; p++) {
            float4 v = *(const float4*)(Qg + (size_t)r * DK + c0 + p * 4);
            float vv[4] = {v.x, v.y, v.z, v.w};
#pragma unroll
            for (int q = 0; q < 4; q++) {
                const float hf = __uint_as_float(f2tf32(vv[q]));
                Qh[r * APAD + c0 + p * 4 + q] = hf;
                Ql[r * APAD + c0 + p * 4 + q] = vv[q] - hf;
            }
        }
    }

    float m_i[2][2], l_i[2][2], o[2][4][4];
#pragma unroll
    for (int mi = 0; mi < 2; mi++)
#pragma unroll
        for (int hf = 0; hf < 2; hf++) { m_i[mi][hf] = -INFINITY; l_i[mi][hf] = 0.f; }
#pragma unroll
    for (int mi = 0; mi < 2; mi++)
#pragma unroll
        for (int ni = 0; ni < 4; ni++)
#pragma unroll
            for (int e = 0; e < 4; e++) o[mi][ni][e] = 0.f;

    const float scale = 0.125f;   // 1/sqrt(64)
    const int jmax = 2 * qi + 1;

    for (int j = 0; j <= jmax; j++) {
        __syncthreads();   // Q load done (iter 0) / prev PV readers done

        // ---- load K,V tiles (64 x 64), split hi/lo ----
        {
            const int r  = tid >> 2;
            const int c0 = (tid & 3) * 16;
#pragma unroll
            for (int p = 0; p < 4; p++) {
                float4 kv = *(const float4*)(Kg + (size_t)(j * KT + r) * DK + c0 + p * 4);
                float4 vv = *(const float4*)(Vg + (size_t)(j * KT + r) * DK + c0 + p * 4);
                float kk[4] = {kv.x, kv.y, kv.z, kv.w};
                float vf[4] = {vv.x, vv.y, vv.z, vv.w};
#pragma unroll
                for (int q = 0; q < 4; q++) {
                    const int c = c0 + p * 4 + q;
                    float hk = __uint_as_float(f2tf32(kk[q]));
                    Kh[r * APAD + c] = hk;
                    Kl[r * APAD + c] = kk[q] - hk;
                    float hv = __uint_as_float(f2tf32(vf[q]));
                    Vh[r * APAD + c] = hv;
                    Vl[r * APAD + c] = vf[q] - hv;
                }
            }
        }
        __syncthreads();

        // ---- S = Q K^T (split tf32) ----
        float s[2][4][4];
#pragma unroll
        for (int mi = 0; mi < 2; mi++)
#pragma unroll
            for (int ni = 0; ni < 4; ni++)
#pragma unroll
                for (int e = 0; e < 4; e++) s[mi][ni][e] = 0.f;

#pragma unroll
        for (int ks = 0; ks < 8; ks++) {
            const int kc = ks * 8 + tig;
            uint32_t ah[2][4], al[2][4];
#pragma unroll
            for (int mi = 0; mi < 2; mi++) {
                const int r0 = wm + mi * 16 + grp;
                ah[mi][0] = __float_as_uint(Qh[r0 * APAD + kc]);
                ah[mi][1] = __float_as_uint(Qh[(r0 + 8) * APAD + kc]);
                ah[mi][2] = __float_as_uint(Qh[r0 * APAD + kc + 4]);
                ah[mi][3] = __float_as_uint(Qh[(r0 + 8) * APAD + kc + 4]);
                al[mi][0] = __float_as_uint(Ql[r0 * APAD + kc]);
                al[mi][1] = __float_as_uint(Ql[(r0 + 8) * APAD + kc]);
                al[mi][2] = __float_as_uint(Ql[r0 * APAD + kc + 4]);
                al[mi][3] = __float_as_uint(Ql[(r0 + 8) * APAD + kc + 4]);
            }
#pragma unroll
            for (int ni = 0; ni < 4; ni++) {
                const int n0 = wn + ni * 8 + grp;
                uint32_t bh[2], bl[2];
                bh[0] = __float_as_uint(Kh[n0 * APAD + kc]);
                bh[1] = __float_as_uint(Kh[n0 * APAD + kc + 4]);
                bl[0] = __float_as_uint(Kl[n0 * APAD + kc]);
                bl[1] = __float_as_uint(Kl[n0 * APAD + kc + 4]);
#pragma unroll
                for (int mi = 0; mi < 2; mi++) {
                    mma_tf32(s[mi][ni], ah[mi], bh);
                    mma_tf32(s[mi][ni], ah[mi], bl);
                    mma_tf32(s[mi][ni], al[mi], bh);
                }
            }
        }

        // ---- scale + causal mask ----
        const bool need_mask = (j >= 2 * qi);
#pragma unroll
        for (int mi = 0; mi < 2; mi++)
#pragma unroll
            for (int ni = 0; ni < 4; ni++)
#pragma unroll
                for (int e = 0; e < 4; e++) {
                    float v = s[mi][ni][e] * scale;
                    if (need_mask) {
                        const int gr = qi * QT + wm + mi * 16 + grp + (e >> 1) * 8;
                        const int gc = j * KT + wn + ni * 8 + tig * 2 + (e & 1);
                        if (gc > gr) v = -INFINITY;
                    }
                    s[mi][ni][e] = v;
                }

        // ---- row max (quad shfl + cross-warp smem) ----
        float rmax[2][2];
#pragma unroll
        for (int mi = 0; mi < 2; mi++)
#pragma unroll
            for (int hf = 0; hf < 2; hf++) {
                float rm = -INFINITY;
#pragma unroll
                for (int ni = 0; ni < 4; ni++)
                    rm = fmaxf(rm, fmaxf(s[mi][ni][hf * 2], s[mi][ni][hf * 2 + 1]));
                rm = fmaxf(rm, __shfl_xor_sync(0xffffffffu, rm, 1));
                rm = fmaxf(rm, __shfl_xor_sync(0xffffffffu, rm, 2));
                rmax[mi][hf] = rm;
                if (tig == 0)
                    redm[warp_n * QT + wm + mi * 16 + grp + hf * 8] = rm;
            }
        __syncthreads();

        // ---- combine max, exp, local sums, P hi/lo write ----
        float alpha_s[2][2];
#pragma unroll
        for (int mi = 0; mi < 2; mi++)
#pragma unroll
            for (int hf = 0; hf < 2; hf++) {
                const int rl = wm + mi * 16 + grp + hf * 8;
                const float nm = fmaxf(m_i[mi][hf], fmaxf(redm[rl], redm[QT + rl]));
                const float alpha = __expf(m_i[mi][hf] - nm);
                m_i[mi][hf] = nm;
                alpha_s[mi][hf] = alpha;
                float rs = 0.f;
#pragma unroll
                for (int ni = 0; ni < 4; ni++) {
                    float p0 = __expf(s[mi][ni][hf * 2 + 0] - nm);
                    float p1 = __expf(s[mi][ni][hf * 2 + 1] - nm);
                    s[mi][ni][hf * 2 + 0] = p0;
                    s[mi][ni][hf * 2 + 1] = p1;
                    rs += p0 + p1;
                }
                rs += __shfl_xor_sync(0xffffffffu, rs, 1);
                rs += __shfl_xor_sync(0xffffffffu, rs, 2);
                if (tig == 0)
                    reds[warp_n * QT + rl] = rs;
                l_i[mi][hf] *= alpha;
#pragma unroll
                for (int ni = 0; ni < 4; ni++) {
                    o[mi][ni][hf * 2 + 0] *= alpha;
                    o[mi][ni][hf * 2 + 1] *= alpha;
                }
            }

        // P -> smem (hi/lo)
#pragma unroll
        for (int mi = 0; mi < 2; mi++)
#pragma unroll
            for (int ni = 0; ni < 4; ni++)
#pragma unroll
                for (int hf = 0; hf < 2; hf++) {
                    const int row = wm + mi * 16 + grp + hf * 8;
                    const int col = wn + ni * 8 + tig * 2;
                    const float p0 = s[mi][ni][hf * 2 + 0];
                    const float p1 = s[mi][ni][hf * 2 + 1];
                    const float h0 = __uint_as_float(f2tf32(p0));
                    const float h1 = __uint_as_float(f2tf32(p1));
                    *(float2*)&Ph[row * APAD + col] = make_float2(h0, h1);
                    *(float2*)&Pl[row * APAD + col] = make_float2(p0 - h0, p1 - h1);
                }
        __syncthreads();

#pragma unroll
        for (int mi = 0; mi < 2; mi++)
#pragma unroll
            for (int hf = 0; hf < 2; hf++) {
                const int rl = wm + mi * 16 + grp + hf * 8;
                l_i[mi][hf] += reds[rl] + reds[QT + rl];
            }

        // ---- O += P V (split tf32) ----
#pragma unroll
        for (int ks = 0; ks < 8; ks++) {
            const int kc = ks * 8 + tig;
            uint32_t ah[2][4], al[2][4];
#pragma unroll
            for (int mi = 0; mi < 2; mi++) {
                const int r0 = wm + mi * 16 + grp;
                ah[mi][0] = __float_as_uint(Ph[r0 * APAD + kc]);
                ah[mi][1] = __float_as_uint(Ph[(r0 + 8) * APAD + kc]);
                ah[mi][2] = __float_as_uint(Ph[r0 * APAD + kc + 4]);
                ah[mi][3] = __float_as_uint(Ph[(r0 + 8) * APAD + kc + 4]);
                al[mi][0] = __float_as_uint(Pl[r0 * APAD + kc]);
                al[mi][1] = __float_as_uint(Pl[(r0 + 8) * APAD + kc]);
                al[mi][2] = __float_as_uint(Pl[r0 * APAD + kc + 4]);
                al[mi][3] = __float_as_uint(Pl[(r0 + 8) * APAD + kc + 4]);
            }
#pragma unroll
            for (int ni = 0; ni < 4; ni++) {
                const int n0 = wn + ni * 8 + grp;
                uint32_t bh[2], bl[2];
                bh[0] = __float_as_uint(Vh[(ks * 8 + tig) * APAD + n0]);
                bh[1] = __float_as_uint(Vh[(ks * 8 + tig + 4) * APAD + n0]);
                bl[0] = __float_as_uint(Vl[(ks * 8 + tig) * APAD + n0]);
                bl[1] = __float_as_uint(Vl[(ks * 8 + tig + 4) * APAD + n0]);
#pragma unroll
                for (int mi = 0; mi < 2; mi++) {
                    mma_tf32(o[mi][ni], ah[mi], bh);
                    mma_tf32(o[mi][ni], ah[mi], bl);
                    mma_tf32(o[mi][ni], al[mi], bh);
                }
            }
        }
    }

    // ---- epilogue: normalize, write (B, S, D) layout ----
#pragma unroll
    for (int mi = 0; mi < 2; mi++)
#pragma unroll
        for (int hf = 0; hf < 2; hf++) {
            const float inv = 1.f / l_i[mi][hf];
            const int srow = qi * QT + wm + mi * 16 + grp + hf * 8;
#pragma unroll
            for (int ni = 0; ni < 4; ni++) {
                const int col = h * DK + wn + ni * 8 + tig * 2;
                float2 v = make_float2(o[mi][ni][hf * 2 + 0] * inv,
                                       o[mi][ni][hf * 2 + 1] * inv);
                *(float2*)&g_attn[((size_t)(b * SEQ) + srow) * DM + col] = v;
            }
        }
}

// ---------------------------------------------------------------------------

extern "C" void kernel_launch(void* const* d_in, const int* in_sizes, int n_in,
                              void* d_out, int out_size)
{
    const float* x  = (const float*)d_in[0];
    const float* Wq = (const float*)d_in[1];
    const float* bq = (const float*)d_in[2];
    const float* Wk = (const float*)d_in[3];
    const float* bk = (const float*)d_in[4];
    const float* Wv = (const float*)d_in[5];
    const float* bv = (const float*)d_in[6];
    const float* Wo = (const float*)d_in[7];
    const float* bo = (const float*)d_in[8];
    float* out = (float*)d_out;

    float *qp, *kp, *vp, *ap;
    cudaGetSymbolAddress((void**)&qp, g_q);
    cudaGetSymbolAddress((void**)&kp, g_k);
    cudaGetSymbolAddress((void**)&vp, g_v);
    cudaGetSymbolAddress((void**)&ap, g_attn);

    const dim3 ggrid(DM / 128, MTOT / 128);
    const int gemm_smem = 4 * 32 * LDA * (int)sizeof(float);

    cudaFuncSetAttribute(gemm_tf32<true>,  cudaFuncAttributeMaxDynamicSharedMemorySize, gemm_smem);
    cudaFuncSetAttribute(gemm_tf32<false>, cudaFuncAttributeMaxDynamicSharedMemorySize, gemm_smem);

    gemm_tf32<true><<<ggrid, 256, gemm_smem>>>(x, Wq, bq, qp);
    gemm_tf32<true><<<ggrid, 256, gemm_smem>>>(x, Wk, bk, kp);
    gemm_tf32<true><<<ggrid, 256, gemm_smem>>>(x, Wv, bv, vp);

    // attn smem: Q(2) + K(2) + V(2) + P(2) tiles + 2 reduce buffers
    const int attn_smem = (2 * QT * APAD + 4 * KT * APAD + 2 * QT * APAD + 4 * QT)
                          * (int)sizeof(float);   // 210,944 B
    cudaFuncSetAttribute(attn_mma, cudaFuncAttributeMaxDynamicSharedMemorySize,
                         attn_smem);
    attn_mma<<<dim3(SEQ / QT, NH, BATCH), 256, attn_smem>>>();

    gemm_tf32<false><<<ggrid, 256, gemm_smem>>>(ap, Wo, bo, out);
}